// round 15
// baseline (speedup 1.0000x reference)
#include <cuda_runtime.h>

// InputDefenseLayer: y[b,0,c] = clip(x[b,0,c]); y[b,t,c] = 0.25*clip(x[b,t,c]) + 0.75*y[b,t-1,c]
//
// Chunked scan with halo warmup. 0.75^32 ~ 1e-4 -> init error contributes rel_err
// ~3e-5 (measured 2.8e-7 at HALO=48 calibrates the model: rel_err ~ 0.34*0.75^HALO),
// 35x under the 1e-3 gate. 32 chunks x 64 batches = 2048 CTAs of 64 threads
// (~24+ warps/SM, vs 14 in R13) for latency coverage. 8-deep ping-pong register
// prefetch (no copy shuffle) keeps 8 LDG.128 in flight per thread.

static constexpr int B_DIM  = 64;
static constexpr int T_DIM  = 2048;
static constexpr int C4     = 64;            // 256 channels / 4 = float4 lanes per row

static constexpr int CHUNK  = 64;            // stored timesteps per unit
static constexpr int HALO   = 32;            // warmup steps
static constexpr int NCHUNK = T_DIM / CHUNK; // 32
static constexpr int U      = 8;             // pipeline group size

static constexpr float A_COEF = 0.25f;
static constexpr float B_COEF = 0.75f;
static constexpr float CLIP_MIN = -3.5f;
static constexpr float CLIP_MAX =  3.5f;

__device__ __forceinline__ float4 clip4(float4 v) {
    v.x = fminf(fmaxf(v.x, CLIP_MIN), CLIP_MAX);
    v.y = fminf(fmaxf(v.y, CLIP_MIN), CLIP_MAX);
    v.z = fminf(fmaxf(v.z, CLIP_MIN), CLIP_MAX);
    v.w = fminf(fmaxf(v.w, CLIP_MIN), CLIP_MAX);
    return v;
}

// Serial chain is a single FMA per step: A*x is independent of s.
__device__ __forceinline__ float4 ema4(float4 s, float4 x) {
    s.x = fmaf(B_COEF, s.x, A_COEF * x.x);
    s.y = fmaf(B_COEF, s.y, A_COEF * x.y);
    s.z = fmaf(B_COEF, s.z, A_COEF * x.z);
    s.w = fmaf(B_COEF, s.w, A_COEF * x.w);
    return s;
}

__global__ __launch_bounds__(64, 12)
void ema_scan_kernel(const float4* __restrict__ x, float4* __restrict__ y) {
    const int unit  = blockIdx.x;            // 0 .. B_DIM*NCHUNK-1
    const int b     = unit >> 5;             // unit / NCHUNK
    const int chunk = unit & (NCHUNK - 1);
    const int lane  = threadIdx.x;           // 0 .. 63

    const float4* __restrict__ xi = x + (size_t)b * T_DIM * C4 + lane;
    float4*       __restrict__ yo = y + (size_t)b * T_DIM * C4 + lane;

    const int t0     = chunk * CHUNK;                  // first stored timestep
    const int tstart = (chunk == 0) ? 0 : (t0 - HALO); // first loaded timestep
    const int tEnd   = t0 + CHUNK;

    // Init. Exact for chunk 0; for others error decays by 0.75^HALO before first store.
    float4 s = clip4(xi[(size_t)tstart * C4]);
    if (chunk == 0) __stcs(&yo[0], s);

    // 7-step prologue: remaining step count (63 or 95 -> 56 or 88) becomes a multiple of U.
    #pragma unroll
    for (int j = 1; j <= 7; ++j) {
        s = ema4(s, clip4(xi[(size_t)(tstart + j) * C4]));
        if (chunk == 0) __stcs(&yo[(size_t)j * C4], s);
    }

    int tc = tstart + 8;                      // next compute timestep
    const int nGroups = (tEnd - tc) >> 3;     // 7 (chunk 0) or 11

    float4 buf0[U], buf1[U];
    #pragma unroll
    for (int j = 0; j < U; ++j) buf0[j] = xi[(size_t)(tc + j) * C4];

    int g = 0;
    while (true) {
        // compute buf0 group, prefetch into buf1
        {
            const bool more = (g + 1 < nGroups);
            if (more) {
                #pragma unroll
                for (int j = 0; j < U; ++j) buf1[j] = xi[(size_t)(tc + U + j) * C4];
            }
            #pragma unroll
            for (int j = 0; j < U; ++j) {
                s = ema4(s, clip4(buf0[j]));
                if (tc + j >= t0) __stcs(&yo[(size_t)(tc + j) * C4], s);
            }
            tc += U; ++g;
            if (!more) break;
        }
        // compute buf1 group, prefetch into buf0
        {
            const bool more = (g + 1 < nGroups);
            if (more) {
                #pragma unroll
                for (int j = 0; j < U; ++j) buf0[j] = xi[(size_t)(tc + U + j) * C4];
            }
            #pragma unroll
            for (int j = 0; j < U; ++j) {
                s = ema4(s, clip4(buf1[j]));
                if (tc + j >= t0) __stcs(&yo[(size_t)(tc + j) * C4], s);
            }
            tc += U; ++g;
            if (!more) break;
        }
    }
}

extern "C" void kernel_launch(void* const* d_in, const int* in_sizes, int n_in,
                              void* d_out, int out_size) {
    const float4* x = (const float4*)d_in[0];
    float4*       y = (float4*)d_out;
    ema_scan_kernel<<<B_DIM * NCHUNK, 64>>>(x, y);
}

// round 16
// speedup vs baseline: 1.1198x; 1.1198x over previous
#include <cuda_runtime.h>

// InputDefenseLayer: y[b,0,c] = clip(x[b,0,c]); y[b,t,c] = 0.25*clip(x[b,t,c]) + 0.75*y[b,t-1,c]
//
// Chunked scan with halo warmup. Error model calibrated on-silicon:
// rel_err ~ 0.3*0.75^HALO (HALO=48 -> 2.8e-7 measured; HALO=32 -> 3.9e-5 measured),
// so HALO=32 keeps a 25x margin under the 1e-3 gate.
// Config: CHUNK=128 (halo = 25% of stored steps; long pipelines amortize the
// prefetch prologue), 16 chunks x 64 batches = 1024 CTAs x 64 threads, one float4
// lane per thread (fully coalesced 1KB rows). 8-deep copy-free ping-pong register
// prefetch keeps 8 LDG.128 in flight per thread (R13-validated: DRAM 74.7%).
// Caching loads for x (input ~fits 126MB L2; halo re-reads hit), streaming stores
// for y (never re-read; don't evict the halo window).

static constexpr int B_DIM  = 64;
static constexpr int T_DIM  = 2048;
static constexpr int C4     = 64;            // 256 channels / 4 = float4 lanes per row

static constexpr int CHUNK  = 128;           // stored timesteps per unit
static constexpr int HALO   = 32;            // warmup steps
static constexpr int NCHUNK = T_DIM / CHUNK; // 16
static constexpr int U      = 8;             // pipeline group size

static constexpr float A_COEF = 0.25f;
static constexpr float B_COEF = 0.75f;
static constexpr float CLIP_MIN = -3.5f;
static constexpr float CLIP_MAX =  3.5f;

__device__ __forceinline__ float4 clip4(float4 v) {
    v.x = fminf(fmaxf(v.x, CLIP_MIN), CLIP_MAX);
    v.y = fminf(fmaxf(v.y, CLIP_MIN), CLIP_MAX);
    v.z = fminf(fmaxf(v.z, CLIP_MIN), CLIP_MAX);
    v.w = fminf(fmaxf(v.w, CLIP_MIN), CLIP_MAX);
    return v;
}

// Serial chain is a single FMA per step: A*x is independent of s.
__device__ __forceinline__ float4 ema4(float4 s, float4 x) {
    s.x = fmaf(B_COEF, s.x, A_COEF * x.x);
    s.y = fmaf(B_COEF, s.y, A_COEF * x.y);
    s.z = fmaf(B_COEF, s.z, A_COEF * x.z);
    s.w = fmaf(B_COEF, s.w, A_COEF * x.w);
    return s;
}

__global__ __launch_bounds__(64)
void ema_scan_kernel(const float4* __restrict__ x, float4* __restrict__ y) {
    const int unit  = blockIdx.x;            // 0 .. B_DIM*NCHUNK-1
    const int b     = unit >> 4;             // unit / NCHUNK
    const int chunk = unit & (NCHUNK - 1);
    const int lane  = threadIdx.x;           // 0 .. 63

    const float4* __restrict__ xi = x + (size_t)b * T_DIM * C4 + lane;
    float4*       __restrict__ yo = y + (size_t)b * T_DIM * C4 + lane;

    const int t0     = chunk * CHUNK;                  // first stored timestep
    const int tstart = (chunk == 0) ? 0 : (t0 - HALO); // first loaded timestep
    const int tEnd   = t0 + CHUNK;

    // Init. Exact for chunk 0; for others error decays by 0.75^HALO before first store.
    float4 s = clip4(xi[(size_t)tstart * C4]);
    if (chunk == 0) __stcs(&yo[0], s);

    // 7-step prologue: remaining step count (127 or 159 -> 120 or 152) is a multiple of U.
    #pragma unroll
    for (int j = 1; j <= 7; ++j) {
        s = ema4(s, clip4(xi[(size_t)(tstart + j) * C4]));
        if (chunk == 0) __stcs(&yo[(size_t)j * C4], s);
    }

    int tc = tstart + 8;                      // next compute timestep
    const int nGroups = (tEnd - tc) >> 3;     // 15 (chunk 0) or 19

    float4 buf0[U], buf1[U];
    #pragma unroll
    for (int j = 0; j < U; ++j) buf0[j] = xi[(size_t)(tc + j) * C4];

    int g = 0;
    while (true) {
        // compute buf0 group, prefetch into buf1
        {
            const bool more = (g + 1 < nGroups);
            if (more) {
                #pragma unroll
                for (int j = 0; j < U; ++j) buf1[j] = xi[(size_t)(tc + U + j) * C4];
            }
            #pragma unroll
            for (int j = 0; j < U; ++j) {
                s = ema4(s, clip4(buf0[j]));
                if (tc + j >= t0) __stcs(&yo[(size_t)(tc + j) * C4], s);
            }
            tc += U; ++g;
            if (!more) break;
        }
        // compute buf1 group, prefetch into buf0
        {
            const bool more = (g + 1 < nGroups);
            if (more) {
                #pragma unroll
                for (int j = 0; j < U; ++j) buf0[j] = xi[(size_t)(tc + U + j) * C4];
            }
            #pragma unroll
            for (int j = 0; j < U; ++j) {
                s = ema4(s, clip4(buf1[j]));
                if (tc + j >= t0) __stcs(&yo[(size_t)(tc + j) * C4], s);
            }
            tc += U; ++g;
            if (!more) break;
        }
    }
}

extern "C" void kernel_launch(void* const* d_in, const int* in_sizes, int n_in,
                              void* d_out, int out_size) {
    const float4* x = (const float4*)d_in[0];
    float4*       y = (float4*)d_out;
    ema_scan_kernel<<<B_DIM * NCHUNK, 64>>>(x, y);
}